// round 3
// baseline (speedup 1.0000x reference)
#include <cuda_runtime.h>
#include <cuda_bf16.h>

// Problem constants (DRewGIN: N=50000 nodes, E=800000 edges, D=128, L=3)
#define NMAX 50000
#define EMAX 800000
#define DIM  128
#define LAY  3

// ---------------- device scratch (static, no allocation) ----------------
__device__ float g_x1[NMAX * DIM];     // xs[1]
__device__ float g_x2[NMAX * DIM];     // xs[2]
__device__ float g_sout[NMAX * DIM];   // (1+eps)*relu(xt@Ws+bs)
__device__ float g_z0[NMAX * DIM];     // z for k=1
__device__ float g_z1[NMAX * DIM];     // z for k=2
__device__ float g_z2[NMAX * DIM];     // z for k=3
__device__ int g_count[NMAX];
__device__ int g_rowptr[NMAX + 1];
__device__ int g_wptr[NMAX];
__device__ unsigned g_edges[EMAX];     // packed: src (16 bits) | attr<<16

// ---------------- f32x2 helpers ----------------
__device__ __forceinline__ void ffma2(unsigned long long& d, unsigned long long a,
                                      unsigned long long b) {
    asm("fma.rn.f32x2 %0, %1, %2, %0;" : "+l"(d) : "l"(a), "l"(b));
}
__device__ __forceinline__ unsigned long long pack2(float lo, float hi) {
    unsigned long long r;
    asm("mov.b64 %0, {%1, %2};" : "=l"(r) : "f"(lo), "f"(hi));
    return r;
}
__device__ __forceinline__ void unpack2(unsigned long long v, float& lo, float& hi) {
    asm("mov.b64 {%0, %1}, %2;" : "=f"(lo), "=f"(hi) : "l"(v));
}

// ---------------- CSR build ----------------
__global__ void zero_count_k(int n) {
    int i = blockIdx.x * blockDim.x + threadIdx.x;
    if (i < n) g_count[i] = 0;
}

__global__ void count_k(const int* __restrict__ dst, int e) {
    int i = blockIdx.x * blockDim.x + threadIdx.x;
    if (i < e) atomicAdd(&g_count[dst[i]], 1);
}

__global__ void scan_k(int n, int e) {
    __shared__ int sh[1024];
    int tid = threadIdx.x;
    int ch = (n + 1023) >> 10;
    int beg = tid * ch;
    int end = beg + ch; if (end > n) end = n;
    int s = 0;
    for (int i = beg; i < end; i++) s += g_count[i];
    sh[tid] = s;
    __syncthreads();
    for (int off = 1; off < 1024; off <<= 1) {
        int v = (tid >= off) ? sh[tid - off] : 0;
        __syncthreads();
        sh[tid] += v;
        __syncthreads();
    }
    int excl = (tid == 0) ? 0 : sh[tid - 1];
    for (int i = beg; i < end; i++) {
        g_rowptr[i] = excl;
        g_wptr[i] = excl;
        excl += g_count[i];
    }
    if (tid == 0) g_rowptr[n] = e;
}

__global__ void place_k(const int* __restrict__ src, const int* __restrict__ dst,
                        const int* __restrict__ attr, int e) {
    int i = blockIdx.x * blockDim.x + threadIdx.x;
    if (i < e) {
        int pos = atomicAdd(&g_wptr[dst[i]], 1);
        g_edges[pos] = (unsigned)src[i] | ((unsigned)attr[i] << 16);
    }
}

// ---------------- f32x2 GEMM: C[n x 128] = A[n x 128] @ W[128 x 128] ----------------
// Tile 128 rows x 128 cols per 256-thread block. Each thread: 8 rows x 8 cols,
// accumulated as 32 f32x2 (pairs over rows). A stored K-major in smem so the
// a-fragment loads pre-packed as float2; b broadcast packed via mov.b64.
// mode 0: C = A@W ; mode 1: C = (1 + *epsp) * relu(A@W + bias)
__global__ void __launch_bounds__(256, 2)
gemm_k(const float* __restrict__ A, const float* __restrict__ W,
       const float* __restrict__ bias, const float* __restrict__ epsp,
       float* __restrict__ C, int n, int mode) {
    __shared__ float As[16][132];   // [k][row], 132 keeps 16B alignment per row-start
    __shared__ float Bs[16][128];   // [k][col]

    const int br = blockIdx.x * 128;
    const int tid = threadIdx.x;       // 256 threads
    const int tx = tid & 15;           // col group: cols tx*8 .. tx*8+7
    const int ty = tid >> 4;           // row group: rows ty*8 .. ty*8+7

    unsigned long long acc[8][4];      // [col j][row pair r] ; pair = rows (2r, 2r+1)
#pragma unroll
    for (int j = 0; j < 8; j++)
#pragma unroll
        for (int r = 0; r < 4; r++) acc[j][r] = 0ull;

    for (int k0 = 0; k0 < 128; k0 += 16) {
        // --- load A tile: 128 rows x 16 k, store transposed (K-major) ---
#pragma unroll
        for (int jj = 0; jj < 2; jj++) {
            int f = tid + jj * 256;            // 0..511
            int row = f & 127;
            int cg = f >> 7;                   // 0..3
            int grow = br + row;
            float4 av = make_float4(0.f, 0.f, 0.f, 0.f);
            if (grow < n) av = *(const float4*)(A + grow * 128 + k0 + cg * 4);
            As[cg * 4 + 0][row] = av.x;
            As[cg * 4 + 1][row] = av.y;
            As[cg * 4 + 2][row] = av.z;
            As[cg * 4 + 3][row] = av.w;
        }
        // --- load B tile: 16 k x 128 cols ---
#pragma unroll
        for (int jj = 0; jj < 2; jj++) {
            int f = tid + jj * 256;
            int rb = f >> 5;                   // 0..15
            int cb = (f & 31) << 2;
            *(float4*)&Bs[rb][cb] = *(const float4*)(W + (k0 + rb) * 128 + cb);
        }
        __syncthreads();

#pragma unroll
        for (int kk = 0; kk < 16; kk++) {
            // a pairs: rows ty*8..+7 -> 4 packed float2 (8 contiguous floats)
            float4 a01 = *(const float4*)&As[kk][ty * 8];
            float4 a23 = *(const float4*)&As[kk][ty * 8 + 4];
            unsigned long long a2[4];
            a2[0] = pack2(a01.x, a01.y);
            a2[1] = pack2(a01.z, a01.w);
            a2[2] = pack2(a23.x, a23.y);
            a2[3] = pack2(a23.z, a23.w);
            // b: cols tx*8..+7, broadcast-packed
            float4 b03 = *(const float4*)&Bs[kk][tx * 8];
            float4 b47 = *(const float4*)&Bs[kk][tx * 8 + 4];
            float bb[8] = {b03.x, b03.y, b03.z, b03.w, b47.x, b47.y, b47.z, b47.w};
#pragma unroll
            for (int j = 0; j < 8; j++) {
                unsigned long long b2 = pack2(bb[j], bb[j]);
#pragma unroll
                for (int r = 0; r < 4; r++) ffma2(acc[j][r], a2[r], b2);
            }
        }
        __syncthreads();
    }

    float escale = 1.0f;
    if (mode == 1) escale = 1.0f + *epsp;
    float bcol[8];
    if (mode == 1) {
#pragma unroll
        for (int j = 0; j < 8; j++) bcol[j] = bias[tx * 8 + j];
    }
#pragma unroll
    for (int r = 0; r < 4; r++) {
        float lo[8], hi[8];
#pragma unroll
        for (int j = 0; j < 8; j++) unpack2(acc[j][r], lo[j], hi[j]);
        int row0 = br + ty * 8 + 2 * r;
        if (mode == 1) {
#pragma unroll
            for (int j = 0; j < 8; j++) {
                lo[j] = escale * fmaxf(lo[j] + bcol[j], 0.f);
                hi[j] = escale * fmaxf(hi[j] + bcol[j], 0.f);
            }
        }
        if (row0 < n) {
            *(float4*)(C + row0 * 128 + tx * 8)     = make_float4(lo[0], lo[1], lo[2], lo[3]);
            *(float4*)(C + row0 * 128 + tx * 8 + 4) = make_float4(lo[4], lo[5], lo[6], lo[7]);
        }
        if (row0 + 1 < n) {
            *(float4*)(C + (row0 + 1) * 128 + tx * 8)     = make_float4(hi[0], hi[1], hi[2], hi[3]);
            *(float4*)(C + (row0 + 1) * 128 + tx * 8 + 4) = make_float4(hi[4], hi[5], hi[6], hi[7]);
        }
    }
}

// ---------------- fused aggregation + epilogue ----------------
__device__ __forceinline__ float4 relu4(float4 v) {
    return make_float4(fmaxf(v.x, 0.f), fmaxf(v.y, 0.f), fmaxf(v.z, 0.f), fmaxf(v.w, 0.f));
}
__device__ __forceinline__ void add4(float4& a, const float4 b) {
    a.x += b.x; a.y += b.y; a.z += b.z; a.w += b.w;
}

__global__ void aggregate_k(const float* __restrict__ xt, const float* __restrict__ souts,
                            const float* __restrict__ z1, const float* __restrict__ z2,
                            const float* __restrict__ z3, const float* __restrict__ bk_t,
                            int kmax, float* __restrict__ xnext, int n) {
    int warp = (blockIdx.x * blockDim.x + threadIdx.x) >> 5;
    if (warp >= n) return;
    int lane = threadIdx.x & 31;

    float4 acc1 = make_float4(0.f, 0.f, 0.f, 0.f);
    float4 acc2 = acc1, acc3 = acc1;

    int beg = g_rowptr[warp];
    int end = g_rowptr[warp + 1];
    for (int e = beg; e < end; e++) {
        unsigned p = g_edges[e];
        int a = (int)(p >> 16);
        if (a > kmax) continue;
        int src = (int)(p & 0xFFFFu);
        const float4* zp = (const float4*)((a == 1) ? z1 : (a == 2) ? z2 : z3);
        float4 v = zp[src * 32 + lane];
        if (a == 1) add4(acc1, v);
        else if (a == 2) add4(acc2, v);
        else add4(acc3, v);
    }

    float4 o = ((const float4*)souts)[warp * 32 + lane];
    {
        float4 b = ((const float4*)(bk_t + 0 * DIM))[lane];
        add4(acc1, b);
        add4(o, relu4(acc1));
    }
    if (kmax >= 2) {
        float4 b = ((const float4*)(bk_t + 1 * DIM))[lane];
        add4(acc2, b);
        add4(o, relu4(acc2));
    }
    if (kmax >= 3) {
        float4 b = ((const float4*)(bk_t + 2 * DIM))[lane];
        add4(acc3, b);
        add4(o, relu4(acc3));
    }
    float4 xv = ((const float4*)xt)[warp * 32 + lane];
    float4 h = relu4(o);
    add4(xv, h);
    ((float4*)xnext)[warp * 32 + lane] = xv;
}

// ---------------- launch ----------------
extern "C" void kernel_launch(void* const* d_in, const int* in_sizes, int n_in,
                              void* d_out, int out_size) {
    const float* x   = (const float*)d_in[0];
    const int*   ei  = (const int*)d_in[1];   // [2, E]: row0 src, row1 dst
    const int*   ea  = (const int*)d_in[2];   // [E] in {1..3}
    const float* Ws  = (const float*)d_in[3]; // [L, D, D]
    const float* bs  = (const float*)d_in[4]; // [L, D]
    const float* Wk  = (const float*)d_in[5]; // [L, L, D, D]
    const float* bk  = (const float*)d_in[6]; // [L, L, D]
    const float* eps = (const float*)d_in[7]; // [L]
    float* out = (float*)d_out;

    int n = in_sizes[0] / DIM;
    int e = in_sizes[2];
    const int* src = ei;
    const int* dst = ei + e;

    float *p_x1, *p_x2, *p_sout, *p_z0, *p_z1, *p_z2;
    cudaGetSymbolAddress((void**)&p_x1, g_x1);
    cudaGetSymbolAddress((void**)&p_x2, g_x2);
    cudaGetSymbolAddress((void**)&p_sout, g_sout);
    cudaGetSymbolAddress((void**)&p_z0, g_z0);
    cudaGetSymbolAddress((void**)&p_z1, g_z1);
    cudaGetSymbolAddress((void**)&p_z2, g_z2);

    // ----- CSR build -----
    zero_count_k<<<(n + 255) / 256, 256>>>(n);
    count_k<<<(e + 255) / 256, 256>>>(dst, e);
    scan_k<<<1, 1024>>>(n, e);
    place_k<<<(e + 255) / 256, 256>>>(src, dst, ea, e);

    const float* xs[4];
    xs[0] = x;
    xs[1] = p_x1;
    xs[2] = p_x2;
    xs[3] = out;

    int gemm_grid = (n + 127) / 128;
    int agg_grid = (n * 32 + 255) / 256;

    for (int t = 0; t < LAY; t++) {
        // mlp_s: (1+eps)*relu(xt@Ws[t]+bs[t])
        gemm_k<<<gemm_grid, 256>>>(xs[t], Ws + (size_t)t * DIM * DIM,
                                   bs + t * DIM, eps + t, p_sout, n, 1);
        // z_k = xs[t-k+1] @ Wk[t][k-1]
        float* zbuf[3] = {p_z0, p_z1, p_z2};
        for (int k = 1; k <= t + 1; k++) {
            const float* asrc = xs[t - (k - 1)];
            const float* Wkt = Wk + ((size_t)t * LAY + (k - 1)) * DIM * DIM;
            gemm_k<<<gemm_grid, 256>>>(asrc, Wkt, nullptr, nullptr,
                                       zbuf[k - 1], n, 0);
        }
        // fused aggregate + epilogue + residual -> xs[t+1]
        aggregate_k<<<agg_grid, 256>>>(xs[t], p_sout, p_z0, p_z1, p_z2,
                                       bk + (size_t)t * LAY * DIM, t + 1,
                                       (float*)xs[t + 1], n);
    }
}

// round 6
// speedup vs baseline: 1.7130x; 1.7130x over previous
#include <cuda_runtime.h>
#include <cuda_bf16.h>
#include <cstdint>

// Problem constants (DRewGIN: N=50000 nodes, E=800000 edges, D=128, L=3)
#define NMAX 50000
#define EMAX 800000
#define DIM  128
#define LAY  3
#define APITCH 136   // smem row pitch in bf16 elements (272 B -> conflict-free frag loads)

// ---------------- device scratch (static, no allocation) ----------------
__device__ float g_x1[NMAX * DIM];
__device__ float g_x2[NMAX * DIM];
__device__ float g_sout[NMAX * DIM];
__device__ float g_z0[NMAX * DIM];
__device__ float g_z1[NMAX * DIM];
__device__ float g_z2[NMAX * DIM];
__device__ __nv_bfloat16 g_whT[12 * DIM * DIM];  // weight^T hi planes [n][k]
__device__ __nv_bfloat16 g_wlT[12 * DIM * DIM];  // weight^T lo planes [n][k]
__device__ int g_count[NMAX];
__device__ int g_rowptr[NMAX + 1];
__device__ int g_wptr[NMAX];
__device__ unsigned g_edges[EMAX];   // packed: src (16b) | attr<<16

// ---------------- CSR build ----------------
__global__ void zero_count_k(int n) {
    int i = blockIdx.x * blockDim.x + threadIdx.x;
    if (i < n) g_count[i] = 0;
}
__global__ void count_k(const int* __restrict__ dst, int e) {
    int i = blockIdx.x * blockDim.x + threadIdx.x;
    if (i < e) atomicAdd(&g_count[dst[i]], 1);
}
__global__ void scan_k(int n, int e) {
    __shared__ int sh[1024];
    int tid = threadIdx.x;
    int ch = (n + 1023) >> 10;
    int beg = tid * ch;
    int end = beg + ch; if (end > n) end = n;
    int s = 0;
    for (int i = beg; i < end; i++) s += g_count[i];
    sh[tid] = s;
    __syncthreads();
    for (int off = 1; off < 1024; off <<= 1) {
        int v = (tid >= off) ? sh[tid - off] : 0;
        __syncthreads();
        sh[tid] += v;
        __syncthreads();
    }
    int excl = (tid == 0) ? 0 : sh[tid - 1];
    for (int i = beg; i < end; i++) {
        g_rowptr[i] = excl;
        g_wptr[i] = excl;
        excl += g_count[i];
    }
    if (tid == 0) g_rowptr[n] = e;
}
__global__ void place_k(const int* __restrict__ src, const int* __restrict__ dst,
                        const int* __restrict__ attr, int e) {
    int i = blockIdx.x * blockDim.x + threadIdx.x;
    if (i < e) {
        int pos = atomicAdd(&g_wptr[dst[i]], 1);
        g_edges[pos] = (unsigned)src[i] | ((unsigned)attr[i] << 16);
    }
}

// ---------------- weight preprocessing: transpose + bf16 split ----------------
// slot 0..2 -> Ws[t];  slot 3..11 -> Wk flat.  Output [n][k] bf16.
__global__ void convw_k(const float* __restrict__ Ws, const float* __restrict__ Wk) {
    int slot = blockIdx.x;
    const float* W = (slot < 3) ? (Ws + (size_t)slot * DIM * DIM)
                                : (Wk + (size_t)(slot - 3) * DIM * DIM);
    __nv_bfloat16* oh = g_whT + (size_t)slot * DIM * DIM;
    __nv_bfloat16* ol = g_wlT + (size_t)slot * DIM * DIM;
    for (int i = threadIdx.x; i < DIM * DIM; i += blockDim.x) {
        int nn = i >> 7, kk = i & 127;
        float w = W[kk * DIM + nn];
        __nv_bfloat16 h = __float2bfloat16(w);
        __nv_bfloat16 l = __float2bfloat16(w - __bfloat162float(h));
        oh[i] = h;
        ol[i] = l;
    }
}

// ---------------- HMMA bf16-split GEMM ----------------
// C[n x 128] = A[n x 128] @ W ; W given as transposed bf16 planes [n][k].
// mode 0: C = A@W ; mode 1: C = (1 + *epsp) * relu(A@W + bias)
__device__ __forceinline__ void mma16816(float* d, const uint32_t* a, const uint32_t* b) {
    asm volatile(
        "mma.sync.aligned.m16n8k16.row.col.f32.bf16.bf16.f32 "
        "{%0,%1,%2,%3}, {%4,%5,%6,%7}, {%8,%9}, {%0,%1,%2,%3};"
        : "+f"(d[0]), "+f"(d[1]), "+f"(d[2]), "+f"(d[3])
        : "r"(a[0]), "r"(a[1]), "r"(a[2]), "r"(a[3]), "r"(b[0]), "r"(b[1]));
}

#define SM_BYTES (4 * 128 * APITCH * 2)

__global__ void __launch_bounds__(256, 1)
mma_gemm_k(const float* __restrict__ A, const __nv_bfloat16* __restrict__ WhT,
           const __nv_bfloat16* __restrict__ WlT, const float* __restrict__ bias,
           const float* __restrict__ epsp, float* __restrict__ C, int n, int mode) {
    extern __shared__ __nv_bfloat16 smem[];
    __nv_bfloat16* As_h = smem;                    // [128][APITCH]
    __nv_bfloat16* As_l = As_h + 128 * APITCH;
    __nv_bfloat16* Bs_h = As_l + 128 * APITCH;
    __nv_bfloat16* Bs_l = Bs_h + 128 * APITCH;

    const int tid = threadIdx.x;
    const int br = blockIdx.x * 128;

    // ---- load W planes: [n][k] bf16, 16B vectors ----
    for (int i = tid; i < 128 * 16; i += 256) {
        int row = i >> 4;
        int c8 = (i & 15) << 3;
        *(uint4*)&Bs_h[row * APITCH + c8] = *(const uint4*)(WhT + row * DIM + c8);
        *(uint4*)&Bs_l[row * APITCH + c8] = *(const uint4*)(WlT + row * DIM + c8);
    }
    // ---- load A: fp32 -> split bf16 hi/lo ----
    for (int i = tid; i < 4096; i += 256) {
        int row = i >> 5;
        int c4 = (i & 31) << 2;
        int gr = br + row;
        float4 v = make_float4(0.f, 0.f, 0.f, 0.f);
        if (gr < n) v = *(const float4*)(A + (size_t)gr * DIM + c4);
        __nv_bfloat16 h0 = __float2bfloat16(v.x), h1 = __float2bfloat16(v.y);
        __nv_bfloat16 h2 = __float2bfloat16(v.z), h3 = __float2bfloat16(v.w);
        __nv_bfloat16 l0 = __float2bfloat16(v.x - __bfloat162float(h0));
        __nv_bfloat16 l1 = __float2bfloat16(v.y - __bfloat162float(h1));
        __nv_bfloat16 l2 = __float2bfloat16(v.z - __bfloat162float(h2));
        __nv_bfloat16 l3 = __float2bfloat16(v.w - __bfloat162float(h3));
        __nv_bfloat162 hA(h0, h1), hB(h2, h3), lA(l0, l1), lB(l2, l3);
        uint2 hu, lu;
        hu.x = *(uint32_t*)&hA; hu.y = *(uint32_t*)&hB;
        lu.x = *(uint32_t*)&lA; lu.y = *(uint32_t*)&lB;
        *(uint2*)&As_h[row * APITCH + c4] = hu;
        *(uint2*)&As_l[row * APITCH + c4] = lu;
    }
    __syncthreads();

    // ---- warp tiling: 8 warps = 2 (m) x 4 (n); warp tile 64 x 32 ----
    const int wid = tid >> 5, lane = tid & 31;
    const int wm = (wid & 1) * 64;
    const int wn = (wid >> 1) * 32;
    const int g = lane >> 2;      // groupID (row within 8)
    const int tg = lane & 3;      // thread-in-group (k/col pairs)

    float acc[4][4][4];
#pragma unroll
    for (int mt = 0; mt < 4; mt++)
#pragma unroll
        for (int nt = 0; nt < 4; nt++)
#pragma unroll
            for (int j = 0; j < 4; j++) acc[mt][nt][j] = 0.f;

#pragma unroll
    for (int kc = 0; kc < 8; kc++) {
        const int kb = kc * 16 + tg * 2;
        uint32_t ah[4][4], al[4][4], bh[4][2], bl[4][2];
#pragma unroll
        for (int mt = 0; mt < 4; mt++) {
            int r = wm + mt * 16 + g;
            ah[mt][0] = *(const uint32_t*)&As_h[r * APITCH + kb];
            ah[mt][1] = *(const uint32_t*)&As_h[(r + 8) * APITCH + kb];
            ah[mt][2] = *(const uint32_t*)&As_h[r * APITCH + kb + 8];
            ah[mt][3] = *(const uint32_t*)&As_h[(r + 8) * APITCH + kb + 8];
            al[mt][0] = *(const uint32_t*)&As_l[r * APITCH + kb];
            al[mt][1] = *(const uint32_t*)&As_l[(r + 8) * APITCH + kb];
            al[mt][2] = *(const uint32_t*)&As_l[r * APITCH + kb + 8];
            al[mt][3] = *(const uint32_t*)&As_l[(r + 8) * APITCH + kb + 8];
        }
#pragma unroll
        for (int nt = 0; nt < 4; nt++) {
            int r = wn + nt * 8 + g;
            bh[nt][0] = *(const uint32_t*)&Bs_h[r * APITCH + kb];
            bh[nt][1] = *(const uint32_t*)&Bs_h[r * APITCH + kb + 8];
            bl[nt][0] = *(const uint32_t*)&Bs_l[r * APITCH + kb];
            bl[nt][1] = *(const uint32_t*)&Bs_l[r * APITCH + kb + 8];
        }
#pragma unroll
        for (int mt = 0; mt < 4; mt++)
#pragma unroll
            for (int nt = 0; nt < 4; nt++) {
                mma16816(acc[mt][nt], ah[mt], bh[nt]);
                mma16816(acc[mt][nt], ah[mt], bl[nt]);
                mma16816(acc[mt][nt], al[mt], bh[nt]);
            }
    }

    // ---- epilogue ----
    float esc = 1.0f;
    if (mode) esc = 1.0f + *epsp;
#pragma unroll
    for (int mt = 0; mt < 4; mt++) {
#pragma unroll
        for (int nt = 0; nt < 4; nt++) {
            int col = wn + nt * 8 + tg * 2;
            int r0 = br + wm + mt * 16 + g;
            float v0 = acc[mt][nt][0], v1 = acc[mt][nt][1];
            float v2 = acc[mt][nt][2], v3 = acc[mt][nt][3];
            if (mode) {
                float b0 = bias[col], b1 = bias[col + 1];
                v0 = esc * fmaxf(v0 + b0, 0.f);
                v1 = esc * fmaxf(v1 + b1, 0.f);
                v2 = esc * fmaxf(v2 + b0, 0.f);
                v3 = esc * fmaxf(v3 + b1, 0.f);
            }
            if (r0 < n)     *(float2*)(C + (size_t)r0 * DIM + col)       = make_float2(v0, v1);
            if (r0 + 8 < n) *(float2*)(C + (size_t)(r0 + 8) * DIM + col) = make_float2(v2, v3);
        }
    }
}

// ---------------- fused aggregation + epilogue ----------------
__device__ __forceinline__ float4 relu4(float4 v) {
    return make_float4(fmaxf(v.x, 0.f), fmaxf(v.y, 0.f), fmaxf(v.z, 0.f), fmaxf(v.w, 0.f));
}
__device__ __forceinline__ void add4(float4& a, const float4 b) {
    a.x += b.x; a.y += b.y; a.z += b.z; a.w += b.w;
}

__global__ void aggregate_k(const float* __restrict__ xt, const float* __restrict__ souts,
                            const float* __restrict__ z1, const float* __restrict__ z2,
                            const float* __restrict__ z3, const float* __restrict__ bk_t,
                            int kmax, float* __restrict__ xnext, int n) {
    int warp = (blockIdx.x * blockDim.x + threadIdx.x) >> 5;
    if (warp >= n) return;
    int lane = threadIdx.x & 31;

    float4 acc1 = make_float4(0.f, 0.f, 0.f, 0.f);
    float4 acc2 = acc1, acc3 = acc1;

    int beg = g_rowptr[warp];
    int end = g_rowptr[warp + 1];
    for (int e = beg; e < end; e++) {
        unsigned p = g_edges[e];
        int a = (int)(p >> 16);
        if (a > kmax) continue;
        int src = (int)(p & 0xFFFFu);
        const float4* zp = (const float4*)((a == 1) ? z1 : (a == 2) ? z2 : z3);
        float4 v = zp[src * 32 + lane];
        if (a == 1) add4(acc1, v);
        else if (a == 2) add4(acc2, v);
        else add4(acc3, v);
    }

    float4 o = ((const float4*)souts)[warp * 32 + lane];
    {
        float4 b = ((const float4*)(bk_t + 0 * DIM))[lane];
        add4(acc1, b);
        add4(o, relu4(acc1));
    }
    if (kmax >= 2) {
        float4 b = ((const float4*)(bk_t + 1 * DIM))[lane];
        add4(acc2, b);
        add4(o, relu4(acc2));
    }
    if (kmax >= 3) {
        float4 b = ((const float4*)(bk_t + 2 * DIM))[lane];
        add4(acc3, b);
        add4(o, relu4(acc3));
    }
    float4 xv = ((const float4*)xt)[warp * 32 + lane];
    float4 h = relu4(o);
    add4(xv, h);
    ((float4*)xnext)[warp * 32 + lane] = xv;
}

// ---------------- launch ----------------
extern "C" void kernel_launch(void* const* d_in, const int* in_sizes, int n_in,
                              void* d_out, int out_size) {
    const float* x   = (const float*)d_in[0];
    const int*   ei  = (const int*)d_in[1];   // [2, E]
    const int*   ea  = (const int*)d_in[2];   // [E]
    const float* Ws  = (const float*)d_in[3];
    const float* bs  = (const float*)d_in[4];
    const float* Wk  = (const float*)d_in[5];
    const float* bk  = (const float*)d_in[6];
    const float* eps = (const float*)d_in[7];
    float* out = (float*)d_out;

    int n = in_sizes[0] / DIM;
    int e = in_sizes[2];
    const int* src = ei;
    const int* dst = ei + e;

    float *p_x1, *p_x2, *p_sout, *p_z0, *p_z1, *p_z2;
    cudaGetSymbolAddress((void**)&p_x1, g_x1);
    cudaGetSymbolAddress((void**)&p_x2, g_x2);
    cudaGetSymbolAddress((void**)&p_sout, g_sout);
    cudaGetSymbolAddress((void**)&p_z0, g_z0);
    cudaGetSymbolAddress((void**)&p_z1, g_z1);
    cudaGetSymbolAddress((void**)&p_z2, g_z2);
    __nv_bfloat16 *p_wh, *p_wl;
    cudaGetSymbolAddress((void**)&p_wh, g_whT);
    cudaGetSymbolAddress((void**)&p_wl, g_wlT);

    cudaFuncSetAttribute(mma_gemm_k, cudaFuncAttributeMaxDynamicSharedMemorySize, SM_BYTES);

    // ----- weight preprocessing + CSR build -----
    convw_k<<<12, 256>>>(Ws, Wk);
    zero_count_k<<<(n + 255) / 256, 256>>>(n);
    count_k<<<(e + 255) / 256, 256>>>(dst, e);
    scan_k<<<1, 1024>>>(n, e);
    place_k<<<(e + 255) / 256, 256>>>(src, dst, ea, e);

    const float* xs[4];
    xs[0] = x;
    xs[1] = p_x1;
    xs[2] = p_x2;
    xs[3] = out;

    int gemm_grid = (n + 127) / 128;
    int agg_grid = (n * 32 + 255) / 256;

    for (int t = 0; t < LAY; t++) {
        // mlp_s: (1+eps)*relu(xt@Ws[t]+bs[t])   (weight slot t)
        mma_gemm_k<<<gemm_grid, 256, SM_BYTES>>>(
            xs[t], p_wh + (size_t)t * DIM * DIM, p_wl + (size_t)t * DIM * DIM,
            bs + t * DIM, eps + t, p_sout, n, 1);
        // z_k = xs[t-k+1] @ Wk[t][k-1]   (weight slot 3 + t*3 + (k-1))
        float* zbuf[3] = {p_z0, p_z1, p_z2};
        for (int k = 1; k <= t + 1; k++) {
            int slot = 3 + t * LAY + (k - 1);
            mma_gemm_k<<<gemm_grid, 256, SM_BYTES>>>(
                xs[t - (k - 1)], p_wh + (size_t)slot * DIM * DIM,
                p_wl + (size_t)slot * DIM * DIM, nullptr, nullptr,
                zbuf[k - 1], n, 0);
        }
        // fused aggregate + epilogue + residual -> xs[t+1]
        aggregate_k<<<agg_grid, 256>>>(xs[t], p_sout, p_z0, p_z1, p_z2,
                                       bk + (size_t)t * LAY * DIM, t + 1,
                                       (float*)xs[t + 1], n);
    }
}

// round 8
// speedup vs baseline: 1.9422x; 1.1338x over previous
#include <cuda_runtime.h>
#include <cuda_bf16.h>
#include <cstdint>

// Problem constants (DRewGIN: N=50000 nodes, E=800000 edges, D=128, L=3)
#define NMAX 50000
#define EMAX 800000
#define DIM  128
#define LAY  3
#define APITCH 136   // smem row pitch in bf16 elements (272 B -> conflict-free frag loads)

// ---------------- device scratch (static, no allocation) ----------------
__device__ float g_x1[NMAX * DIM];
__device__ float g_x2[NMAX * DIM];
__device__ float g_sout[NMAX * DIM];
__device__ float g_z0[NMAX * DIM];
__device__ float g_z1[NMAX * DIM];
__device__ float g_z2[NMAX * DIM];
__device__ __nv_bfloat16 g_whT[12 * DIM * DIM];  // weight^T hi planes [n][k]
__device__ __nv_bfloat16 g_wlT[12 * DIM * DIM];  // weight^T lo planes [n][k]
__device__ int g_count[NMAX + 64];
__device__ int g_rowptr[NMAX + 1];
__device__ int g_wptr[NMAX];
__device__ int g_bsum[64];
__device__ int g_boff[64];
__device__ unsigned g_edges[EMAX];   // packed: src (16b) | attr<<16

// ---------------- CSR build ----------------
__global__ void zero_count_k(int n) {
    int i = blockIdx.x * blockDim.x + threadIdx.x;
    if (i < n) g_count[i] = 0;
}
__global__ void count_k(const int* __restrict__ dst, int e) {
    int i = blockIdx.x * blockDim.x + threadIdx.x;
    if (i < e) atomicAdd(&g_count[dst[i]], 1);
}

// hierarchical scan: part1 = per-1024-block exclusive scan + block sums
__global__ void scan1_k(int n) {
    __shared__ int wsum[8];
    const int tid = threadIdx.x;               // 256 threads
    const int base = blockIdx.x * 1024 + tid * 4;
    int4 c = make_int4(0, 0, 0, 0);
    if (base < n) c = *(const int4*)&g_count[base];   // n % 4 == 0 -> all-or-none
    int s0 = c.x;
    int s1 = s0 + c.y;
    int s2 = s1 + c.z;
    int s3 = s2 + c.w;                          // thread-local inclusive total
    // warp inclusive scan of s3
    int lane = tid & 31, wid = tid >> 5;
    int v = s3;
#pragma unroll
    for (int off = 1; off < 32; off <<= 1) {
        int u = __shfl_up_sync(0xffffffffu, v, off);
        if (lane >= off) v += u;
    }
    if (lane == 31) wsum[wid] = v;
    __syncthreads();
    if (wid == 0) {
        int w = (lane < 8) ? wsum[lane] : 0;
#pragma unroll
        for (int off = 1; off < 8; off <<= 1) {
            int u = __shfl_up_sync(0xffffffffu, w, off);
            if (lane >= off) w += u;
        }
        if (lane < 8) wsum[lane] = w;
        if (lane == 7) g_bsum[blockIdx.x] = w;  // block total
    }
    __syncthreads();
    int excl = v - s3 + (wid ? wsum[wid - 1] : 0);  // thread exclusive prefix
    if (base < n) {
        g_rowptr[base + 0] = excl;
        g_rowptr[base + 1] = excl + s0;
        g_rowptr[base + 2] = excl + s1;
        g_rowptr[base + 3] = excl + s2;
    }
}
// part2: exclusive scan of <=64 block sums (one warp would do; use 64 threads simple)
__global__ void scan2_k(int nb) {
    int tid = threadIdx.x;   // 64
    int v = (tid < nb) ? g_bsum[tid] : 0;
#pragma unroll
    for (int off = 1; off < 64; off <<= 1) {
        int u = __shfl_up_sync(0xffffffffu, v & 0 | v, off);  // placeholder avoided below
        (void)u;
        break;
    }
    // simple smem scan (64 elems)
    __shared__ int sh[64];
    sh[tid] = v;
    __syncthreads();
    for (int off = 1; off < 64; off <<= 1) {
        int u = (tid >= off) ? sh[tid - off] : 0;
        __syncthreads();
        sh[tid] += u;
        __syncthreads();
    }
    if (tid < nb) g_boff[tid] = sh[tid] - v;   // exclusive
}
// part3: add block offsets, init wptr, set rowptr[n]
__global__ void scan3_k(int n, int e) {
    int i = blockIdx.x * blockDim.x + threadIdx.x;
    if (i < n) {
        int r = g_rowptr[i] + g_boff[i >> 10];
        g_rowptr[i] = r;
        g_wptr[i] = r;
    }
    if (i == 0) g_rowptr[n] = e;
}

__global__ void place_k(const int* __restrict__ src, const int* __restrict__ dst,
                        const int* __restrict__ attr, int e) {
    int i = blockIdx.x * blockDim.x + threadIdx.x;
    if (i < e) {
        int pos = atomicAdd(&g_wptr[dst[i]], 1);
        g_edges[pos] = (unsigned)src[i] | ((unsigned)attr[i] << 16);
    }
}

// ---------------- weight preprocessing: transpose + bf16 split ----------------
__global__ void convw_k(const float* __restrict__ Ws, const float* __restrict__ Wk) {
    int slot = blockIdx.x;
    const float* W = (slot < 3) ? (Ws + (size_t)slot * DIM * DIM)
                                : (Wk + (size_t)(slot - 3) * DIM * DIM);
    __nv_bfloat16* oh = g_whT + (size_t)slot * DIM * DIM;
    __nv_bfloat16* ol = g_wlT + (size_t)slot * DIM * DIM;
    for (int i = threadIdx.x; i < DIM * DIM; i += blockDim.x) {
        int nn = i >> 7, kk = i & 127;
        float w = W[kk * DIM + nn];
        __nv_bfloat16 h = __float2bfloat16(w);
        __nv_bfloat16 l = __float2bfloat16(w - __bfloat162float(h));
        oh[i] = h;
        ol[i] = l;
    }
}

// ---------------- HMMA bf16-split GEMM ----------------
__device__ __forceinline__ void mma16816(float* d, const uint32_t* a, const uint32_t* b) {
    asm volatile(
        "mma.sync.aligned.m16n8k16.row.col.f32.bf16.bf16.f32 "
        "{%0,%1,%2,%3}, {%4,%5,%6,%7}, {%8,%9}, {%0,%1,%2,%3};"
        : "+f"(d[0]), "+f"(d[1]), "+f"(d[2]), "+f"(d[3])
        : "r"(a[0]), "r"(a[1]), "r"(a[2]), "r"(a[3]), "r"(b[0]), "r"(b[1]));
}

#define SM_BYTES (4 * 128 * APITCH * 2)

__global__ void __launch_bounds__(256, 1)
mma_gemm_k(const float* __restrict__ A, const __nv_bfloat16* __restrict__ WhT,
           const __nv_bfloat16* __restrict__ WlT, const float* __restrict__ bias,
           const float* __restrict__ epsp, float* __restrict__ C, int n, int mode) {
    extern __shared__ __nv_bfloat16 smem[];
    __nv_bfloat16* As_h = smem;                    // [128][APITCH]
    __nv_bfloat16* As_l = As_h + 128 * APITCH;
    __nv_bfloat16* Bs_h = As_l + 128 * APITCH;
    __nv_bfloat16* Bs_l = Bs_h + 128 * APITCH;

    const int tid = threadIdx.x;
    const int br = blockIdx.x * 128;

    for (int i = tid; i < 128 * 16; i += 256) {
        int row = i >> 4;
        int c8 = (i & 15) << 3;
        *(uint4*)&Bs_h[row * APITCH + c8] = *(const uint4*)(WhT + row * DIM + c8);
        *(uint4*)&Bs_l[row * APITCH + c8] = *(const uint4*)(WlT + row * DIM + c8);
    }
    for (int i = tid; i < 4096; i += 256) {
        int row = i >> 5;
        int c4 = (i & 31) << 2;
        int gr = br + row;
        float4 v = make_float4(0.f, 0.f, 0.f, 0.f);
        if (gr < n) v = *(const float4*)(A + (size_t)gr * DIM + c4);
        __nv_bfloat16 h0 = __float2bfloat16(v.x), h1 = __float2bfloat16(v.y);
        __nv_bfloat16 h2 = __float2bfloat16(v.z), h3 = __float2bfloat16(v.w);
        __nv_bfloat16 l0 = __float2bfloat16(v.x - __bfloat162float(h0));
        __nv_bfloat16 l1 = __float2bfloat16(v.y - __bfloat162float(h1));
        __nv_bfloat16 l2 = __float2bfloat16(v.z - __bfloat162float(h2));
        __nv_bfloat16 l3 = __float2bfloat16(v.w - __bfloat162float(h3));
        __nv_bfloat162 hA(h0, h1), hB(h2, h3), lA(l0, l1), lB(l2, l3);
        uint2 hu, lu;
        hu.x = *(uint32_t*)&hA; hu.y = *(uint32_t*)&hB;
        lu.x = *(uint32_t*)&lA; lu.y = *(uint32_t*)&lB;
        *(uint2*)&As_h[row * APITCH + c4] = hu;
        *(uint2*)&As_l[row * APITCH + c4] = lu;
    }
    __syncthreads();

    const int wid = tid >> 5, lane = tid & 31;
    const int wm = (wid & 1) * 64;
    const int wn = (wid >> 1) * 32;
    const int g = lane >> 2;
    const int tg = lane & 3;

    float acc[4][4][4];
#pragma unroll
    for (int mt = 0; mt < 4; mt++)
#pragma unroll
        for (int nt = 0; nt < 4; nt++)
#pragma unroll
            for (int j = 0; j < 4; j++) acc[mt][nt][j] = 0.f;

#pragma unroll
    for (int kc = 0; kc < 8; kc++) {
        const int kb = kc * 16 + tg * 2;
        uint32_t ah[4][4], al[4][4], bh[4][2], bl[4][2];
#pragma unroll
        for (int mt = 0; mt < 4; mt++) {
            int r = wm + mt * 16 + g;
            ah[mt][0] = *(const uint32_t*)&As_h[r * APITCH + kb];
            ah[mt][1] = *(const uint32_t*)&As_h[(r + 8) * APITCH + kb];
            ah[mt][2] = *(const uint32_t*)&As_h[r * APITCH + kb + 8];
            ah[mt][3] = *(const uint32_t*)&As_h[(r + 8) * APITCH + kb + 8];
            al[mt][0] = *(const uint32_t*)&As_l[r * APITCH + kb];
            al[mt][1] = *(const uint32_t*)&As_l[(r + 8) * APITCH + kb];
            al[mt][2] = *(const uint32_t*)&As_l[r * APITCH + kb + 8];
            al[mt][3] = *(const uint32_t*)&As_l[(r + 8) * APITCH + kb + 8];
        }
#pragma unroll
        for (int nt = 0; nt < 4; nt++) {
            int r = wn + nt * 8 + g;
            bh[nt][0] = *(const uint32_t*)&Bs_h[r * APITCH + kb];
            bh[nt][1] = *(const uint32_t*)&Bs_h[r * APITCH + kb + 8];
            bl[nt][0] = *(const uint32_t*)&Bs_l[r * APITCH + kb];
            bl[nt][1] = *(const uint32_t*)&Bs_l[r * APITCH + kb + 8];
        }
#pragma unroll
        for (int mt = 0; mt < 4; mt++)
#pragma unroll
            for (int nt = 0; nt < 4; nt++) {
                mma16816(acc[mt][nt], ah[mt], bh[nt]);
                mma16816(acc[mt][nt], ah[mt], bl[nt]);
                mma16816(acc[mt][nt], al[mt], bh[nt]);
            }
    }

    float esc = 1.0f;
    if (mode) esc = 1.0f + *epsp;
#pragma unroll
    for (int mt = 0; mt < 4; mt++) {
#pragma unroll
        for (int nt = 0; nt < 4; nt++) {
            int col = wn + nt * 8 + tg * 2;
            int r0 = br + wm + mt * 16 + g;
            float v0 = acc[mt][nt][0], v1 = acc[mt][nt][1];
            float v2 = acc[mt][nt][2], v3 = acc[mt][nt][3];
            if (mode) {
                float b0 = bias[col], b1 = bias[col + 1];
                v0 = esc * fmaxf(v0 + b0, 0.f);
                v1 = esc * fmaxf(v1 + b1, 0.f);
                v2 = esc * fmaxf(v2 + b0, 0.f);
                v3 = esc * fmaxf(v3 + b1, 0.f);
            }
            if (r0 < n)     *(float2*)(C + (size_t)r0 * DIM + col)       = make_float2(v0, v1);
            if (r0 + 8 < n) *(float2*)(C + (size_t)(r0 + 8) * DIM + col) = make_float2(v2, v3);
        }
    }
}

// ---------------- fused aggregation + epilogue ----------------
__device__ __forceinline__ float4 relu4(float4 v) {
    return make_float4(fmaxf(v.x, 0.f), fmaxf(v.y, 0.f), fmaxf(v.z, 0.f), fmaxf(v.w, 0.f));
}
__device__ __forceinline__ void add4(float4& a, const float4 b) {
    a.x += b.x; a.y += b.y; a.z += b.z; a.w += b.w;
}

__global__ void aggregate_k(const float* __restrict__ xt, const float* __restrict__ souts,
                            const float* __restrict__ z1, const float* __restrict__ z2,
                            const float* __restrict__ z3, const float* __restrict__ bk_t,
                            int kmax, float* __restrict__ xnext, int n) {
    int warp = (blockIdx.x * blockDim.x + threadIdx.x) >> 5;
    if (warp >= n) return;
    int lane = threadIdx.x & 31;

    float4 acc1 = make_float4(0.f, 0.f, 0.f, 0.f);
    float4 acc2 = acc1, acc3 = acc1;

    int beg = g_rowptr[warp];
    int deg = g_rowptr[warp + 1] - beg;

    // chunk-of-32 cooperative edge fetch, shfl broadcast; z gathers pipeline
    for (int base = 0; base < deg; base += 32) {
        int m = min(32, deg - base);
        unsigned ew = 0;
        if (base + lane < deg) ew = g_edges[beg + base + lane];
        for (int i = 0; i < m; i++) {
            unsigned p = __shfl_sync(0xffffffffu, ew, i);
            int a = (int)(p >> 16);
            if (a > kmax) continue;
            int src = (int)(p & 0xFFFFu);
            const float4* zp = (const float4*)((a == 1) ? z1 : (a == 2) ? z2 : z3);
            float4 v = zp[(size_t)src * 32 + lane];
            if (a == 1) add4(acc1, v);
            else if (a == 2) add4(acc2, v);
            else add4(acc3, v);
        }
    }

    float4 o = ((const float4*)souts)[(size_t)warp * 32 + lane];
    {
        float4 b = ((const float4*)(bk_t + 0 * DIM))[lane];
        add4(acc1, b);
        add4(o, relu4(acc1));
    }
    if (kmax >= 2) {
        float4 b = ((const float4*)(bk_t + 1 * DIM))[lane];
        add4(acc2, b);
        add4(o, relu4(acc2));
    }
    if (kmax >= 3) {
        float4 b = ((const float4*)(bk_t + 2 * DIM))[lane];
        add4(acc3, b);
        add4(o, relu4(acc3));
    }
    float4 xv = ((const float4*)xt)[(size_t)warp * 32 + lane];
    float4 h = relu4(o);
    add4(xv, h);
    ((float4*)xnext)[(size_t)warp * 32 + lane] = xv;
}

// ---------------- launch ----------------
extern "C" void kernel_launch(void* const* d_in, const int* in_sizes, int n_in,
                              void* d_out, int out_size) {
    const float* x   = (const float*)d_in[0];
    const int*   ei  = (const int*)d_in[1];   // [2, E]
    const int*   ea  = (const int*)d_in[2];   // [E]
    const float* Ws  = (const float*)d_in[3];
    const float* bs  = (const float*)d_in[4];
    const float* Wk  = (const float*)d_in[5];
    const float* bk  = (const float*)d_in[6];
    const float* eps = (const float*)d_in[7];
    float* out = (float*)d_out;

    int n = in_sizes[0] / DIM;
    int e = in_sizes[2];
    const int* src = ei;
    const int* dst = ei + e;

    float *p_x1, *p_x2, *p_sout, *p_z0, *p_z1, *p_z2;
    cudaGetSymbolAddress((void**)&p_x1, g_x1);
    cudaGetSymbolAddress((void**)&p_x2, g_x2);
    cudaGetSymbolAddress((void**)&p_sout, g_sout);
    cudaGetSymbolAddress((void**)&p_z0, g_z0);
    cudaGetSymbolAddress((void**)&p_z1, g_z1);
    cudaGetSymbolAddress((void**)&p_z2, g_z2);
    __nv_bfloat16 *p_wh, *p_wl;
    cudaGetSymbolAddress((void**)&p_wh, g_whT);
    cudaGetSymbolAddress((void**)&p_wl, g_wlT);

    cudaFuncSetAttribute(mma_gemm_k, cudaFuncAttributeMaxDynamicSharedMemorySize, SM_BYTES);

    // ----- weight preprocessing + CSR build -----
    convw_k<<<12, 256>>>(Ws, Wk);
    zero_count_k<<<(n + 255) / 256, 256>>>(n);
    count_k<<<(e + 255) / 256, 256>>>(dst, e);
    int nb = (n + 1023) / 1024;          // 49 for n=50000
    scan1_k<<<nb, 256>>>(n);
    scan2_k<<<1, 64>>>(nb);
    scan3_k<<<(n + 255) / 256, 256>>>(n, e);
    place_k<<<(e + 255) / 256, 256>>>(src, dst, ea, e);

    const float* xs[4];
    xs[0] = x;
    xs[1] = p_x1;
    xs[2] = p_x2;
    xs[3] = out;

    int gemm_grid = (n + 127) / 128;
    int agg_grid = (n * 32 + 255) / 256;

    for (int t = 0; t < LAY; t++) {
        mma_gemm_k<<<gemm_grid, 256, SM_BYTES>>>(
            xs[t], p_wh + (size_t)t * DIM * DIM, p_wl + (size_t)t * DIM * DIM,
            bs + t * DIM, eps + t, p_sout, n, 1);
        float* zbuf[3] = {p_z0, p_z1, p_z2};
        for (int k = 1; k <= t + 1; k++) {
            int slot = 3 + t * LAY + (k - 1);
            mma_gemm_k<<<gemm_grid, 256, SM_BYTES>>>(
                xs[t - (k - 1)], p_wh + (size_t)slot * DIM * DIM,
                p_wl + (size_t)slot * DIM * DIM, nullptr, nullptr,
                zbuf[k - 1], n, 0);
        }
        aggregate_k<<<agg_grid, 256>>>(xs[t], p_sout, p_z0, p_z1, p_z2,
                                       bk + (size_t)t * LAY * DIM, t + 1,
                                       (float*)xs[t + 1], n);
    }
}

// round 9
// speedup vs baseline: 2.2425x; 1.1546x over previous
#include <cuda_runtime.h>
#include <cuda_bf16.h>
#include <cstdint>

// Problem constants (DRewGIN: N=50000 nodes, E=800000 edges, D=128, L=3)
#define NMAX 50000
#define EMAX 800000
#define DIM  128
#define LAY  3
#define APITCH 136   // smem row pitch in bf16 elements (272 B -> conflict-free frag loads)

// ---------------- device scratch (static, no allocation) ----------------
__device__ float g_x1[NMAX * DIM];
__device__ float g_x2[NMAX * DIM];
__device__ float g_sout[NMAX * DIM];
__device__ float g_z0[NMAX * DIM];
__device__ float g_z1[NMAX * DIM];
__device__ float g_z2[NMAX * DIM];
__device__ __nv_bfloat16 g_whT[12 * DIM * DIM];  // weight^T hi planes [n][k]
__device__ __nv_bfloat16 g_wlT[12 * DIM * DIM];  // weight^T lo planes [n][k]
__device__ int g_count[NMAX + 64];
__device__ int g_rowptr[NMAX + 1];
__device__ int g_wptr[NMAX];
__device__ int g_bsum[64];
__device__ int g_boff[64];
__device__ unsigned g_edges[EMAX];   // packed: src (16b) | attr<<16

// ---------------- CSR build ----------------
__global__ void zero_count_k(int n) {
    int i = blockIdx.x * blockDim.x + threadIdx.x;
    if (i < n) g_count[i] = 0;
}
__global__ void count_k(const int* __restrict__ dst, int e) {
    int i = blockIdx.x * blockDim.x + threadIdx.x;
    if (i < e) atomicAdd(&g_count[dst[i]], 1);
}

// hierarchical scan
__global__ void scan1_k(int n) {
    __shared__ int wsum[8];
    const int tid = threadIdx.x;               // 256 threads
    const int base = blockIdx.x * 1024 + tid * 4;
    int4 c = make_int4(0, 0, 0, 0);
    if (base < n) c = *(const int4*)&g_count[base];
    int s0 = c.x;
    int s1 = s0 + c.y;
    int s2 = s1 + c.z;
    int s3 = s2 + c.w;
    int lane = tid & 31, wid = tid >> 5;
    int v = s3;
#pragma unroll
    for (int off = 1; off < 32; off <<= 1) {
        int u = __shfl_up_sync(0xffffffffu, v, off);
        if (lane >= off) v += u;
    }
    if (lane == 31) wsum[wid] = v;
    __syncthreads();
    if (wid == 0) {
        int w = (lane < 8) ? wsum[lane] : 0;
#pragma unroll
        for (int off = 1; off < 8; off <<= 1) {
            int u = __shfl_up_sync(0xffffffffu, w, off);
            if (lane >= off) w += u;
        }
        if (lane < 8) wsum[lane] = w;
        if (lane == 7) g_bsum[blockIdx.x] = w;
    }
    __syncthreads();
    int excl = v - s3 + (wid ? wsum[wid - 1] : 0);
    if (base < n) {
        g_rowptr[base + 0] = excl;
        g_rowptr[base + 1] = excl + s0;
        g_rowptr[base + 2] = excl + s1;
        g_rowptr[base + 3] = excl + s2;
    }
}
__global__ void scan2_k(int nb) {
    int tid = threadIdx.x;   // 64
    int v = (tid < nb) ? g_bsum[tid] : 0;
    __shared__ int sh[64];
    sh[tid] = v;
    __syncthreads();
    for (int off = 1; off < 64; off <<= 1) {
        int u = (tid >= off) ? sh[tid - off] : 0;
        __syncthreads();
        sh[tid] += u;
        __syncthreads();
    }
    if (tid < nb) g_boff[tid] = sh[tid] - v;
}
__global__ void scan3_k(int n, int e) {
    int i = blockIdx.x * blockDim.x + threadIdx.x;
    if (i < n) {
        int r = g_rowptr[i] + g_boff[i >> 10];
        g_rowptr[i] = r;
        g_wptr[i] = r;
    }
    if (i == 0) g_rowptr[n] = e;
}

__global__ void place_k(const int* __restrict__ src, const int* __restrict__ dst,
                        const int* __restrict__ attr, int e) {
    int i = blockIdx.x * blockDim.x + threadIdx.x;
    if (i < e) {
        int pos = atomicAdd(&g_wptr[dst[i]], 1);
        g_edges[pos] = (unsigned)src[i] | ((unsigned)attr[i] << 16);
    }
}

// ---------------- weight preprocessing: transpose + bf16 split ----------------
__global__ void convw_k(const float* __restrict__ Ws, const float* __restrict__ Wk) {
    int slot = blockIdx.x;
    const float* W = (slot < 3) ? (Ws + (size_t)slot * DIM * DIM)
                                : (Wk + (size_t)(slot - 3) * DIM * DIM);
    __nv_bfloat16* oh = g_whT + (size_t)slot * DIM * DIM;
    __nv_bfloat16* ol = g_wlT + (size_t)slot * DIM * DIM;
    for (int i = threadIdx.x; i < DIM * DIM; i += blockDim.x) {
        int nn = i >> 7, kk = i & 127;
        float w = W[kk * DIM + nn];
        __nv_bfloat16 h = __float2bfloat16(w);
        __nv_bfloat16 l = __float2bfloat16(w - __bfloat162float(h));
        oh[i] = h;
        ol[i] = l;
    }
}

// ---------------- HMMA bf16-split GEMM (M=64 tile, up to 2 products per launch) ----------------
__device__ __forceinline__ void mma16816(float* d, const uint32_t* a, const uint32_t* b) {
    asm volatile(
        "mma.sync.aligned.m16n8k16.row.col.f32.bf16.bf16.f32 "
        "{%0,%1,%2,%3}, {%4,%5,%6,%7}, {%8,%9}, {%0,%1,%2,%3};"
        : "+f"(d[0]), "+f"(d[1]), "+f"(d[2]), "+f"(d[3])
        : "r"(a[0]), "r"(a[1]), "r"(a[2]), "r"(a[3]), "r"(b[0]), "r"(b[1]));
}

// smem: A planes 2 x 64 x APITCH, B planes 2 x 128 x APITCH  (bf16)
#define SM2_BYTES ((2 * 64 + 2 * 128) * APITCH * 2)

__global__ void __launch_bounds__(128, 2)
mma_gemm2_k(const float* __restrict__ A,
            const __nv_bfloat16* __restrict__ Wh0, const __nv_bfloat16* __restrict__ Wl0,
            float* __restrict__ C0, const float* __restrict__ bias,
            const float* __restrict__ epsp,
            const __nv_bfloat16* __restrict__ Wh1, const __nv_bfloat16* __restrict__ Wl1,
            float* __restrict__ C1, int n) {
    extern __shared__ __nv_bfloat16 smem[];
    __nv_bfloat16* As_h = smem;                        // [64][APITCH]
    __nv_bfloat16* As_l = As_h + 64 * APITCH;
    __nv_bfloat16* Bs_h = As_l + 64 * APITCH;          // [128][APITCH]
    __nv_bfloat16* Bs_l = Bs_h + 128 * APITCH;

    const int tid = threadIdx.x;                       // 128 threads
    const int br = blockIdx.x * 64;
    const int wid = tid >> 5, lane = tid & 31;
    const int wm = (wid & 1) * 32;                     // 2 warps in m
    const int wn = (wid >> 1) * 64;                    // 2 warps in n
    const int g = lane >> 2;
    const int tg = lane & 3;

    // ---- load A tile (64 x 128 fp32) and split to bf16 hi/lo ----
    for (int i = tid; i < 2048; i += 128) {
        int row = i >> 5;
        int c4 = (i & 31) << 2;
        int gr = br + row;
        float4 v = make_float4(0.f, 0.f, 0.f, 0.f);
        if (gr < n) v = *(const float4*)(A + (size_t)gr * DIM + c4);
        __nv_bfloat16 h0 = __float2bfloat16(v.x), h1 = __float2bfloat16(v.y);
        __nv_bfloat16 h2 = __float2bfloat16(v.z), h3 = __float2bfloat16(v.w);
        __nv_bfloat16 l0 = __float2bfloat16(v.x - __bfloat162float(h0));
        __nv_bfloat16 l1 = __float2bfloat16(v.y - __bfloat162float(h1));
        __nv_bfloat16 l2 = __float2bfloat16(v.z - __bfloat162float(h2));
        __nv_bfloat16 l3 = __float2bfloat16(v.w - __bfloat162float(h3));
        __nv_bfloat162 hA(h0, h1), hB(h2, h3), lA(l0, l1), lB(l2, l3);
        uint2 hu, lu;
        hu.x = *(uint32_t*)&hA; hu.y = *(uint32_t*)&hB;
        lu.x = *(uint32_t*)&lA; lu.y = *(uint32_t*)&lB;
        *(uint2*)&As_h[row * APITCH + c4] = hu;
        *(uint2*)&As_l[row * APITCH + c4] = lu;
    }

    const int nprod = (Wh1 != nullptr) ? 2 : 1;
    for (int p = 0; p < nprod; p++) {
        const __nv_bfloat16* Wh = p ? Wh1 : Wh0;
        const __nv_bfloat16* Wl = p ? Wl1 : Wl0;
        float* C = p ? C1 : C0;

        // ---- load B planes (128 x 128 bf16) ----
        __syncthreads();   // protects As on p=0, previous-product Bs reads on p=1
        for (int i = tid; i < 128 * 16; i += 128) {
            int row = i >> 4;
            int c8 = (i & 15) << 3;
            *(uint4*)&Bs_h[row * APITCH + c8] = *(const uint4*)(Wh + row * DIM + c8);
            *(uint4*)&Bs_l[row * APITCH + c8] = *(const uint4*)(Wl + row * DIM + c8);
        }
        __syncthreads();

        float acc[2][8][4];
#pragma unroll
        for (int mt = 0; mt < 2; mt++)
#pragma unroll
            for (int nt = 0; nt < 8; nt++)
#pragma unroll
                for (int j = 0; j < 4; j++) acc[mt][nt][j] = 0.f;

#pragma unroll
        for (int kc = 0; kc < 8; kc++) {
            const int kb = kc * 16 + tg * 2;
            uint32_t ah[2][4], al[2][4], bh[8][2], bl[8][2];
#pragma unroll
            for (int mt = 0; mt < 2; mt++) {
                int r = wm + mt * 16 + g;
                ah[mt][0] = *(const uint32_t*)&As_h[r * APITCH + kb];
                ah[mt][1] = *(const uint32_t*)&As_h[(r + 8) * APITCH + kb];
                ah[mt][2] = *(const uint32_t*)&As_h[r * APITCH + kb + 8];
                ah[mt][3] = *(const uint32_t*)&As_h[(r + 8) * APITCH + kb + 8];
                al[mt][0] = *(const uint32_t*)&As_l[r * APITCH + kb];
                al[mt][1] = *(const uint32_t*)&As_l[(r + 8) * APITCH + kb];
                al[mt][2] = *(const uint32_t*)&As_l[r * APITCH + kb + 8];
                al[mt][3] = *(const uint32_t*)&As_l[(r + 8) * APITCH + kb + 8];
            }
#pragma unroll
            for (int nt = 0; nt < 8; nt++) {
                int r = wn + nt * 8 + g;
                bh[nt][0] = *(const uint32_t*)&Bs_h[r * APITCH + kb];
                bh[nt][1] = *(const uint32_t*)&Bs_h[r * APITCH + kb + 8];
                bl[nt][0] = *(const uint32_t*)&Bs_l[r * APITCH + kb];
                bl[nt][1] = *(const uint32_t*)&Bs_l[r * APITCH + kb + 8];
            }
#pragma unroll
            for (int mt = 0; mt < 2; mt++)
#pragma unroll
                for (int nt = 0; nt < 8; nt++) {
                    mma16816(acc[mt][nt], ah[mt], bh[nt]);
                    mma16816(acc[mt][nt], ah[mt], bl[nt]);
                    mma16816(acc[mt][nt], al[mt], bh[nt]);
                }
        }

        // ---- epilogue ----
        const bool biased = (p == 0) && (bias != nullptr);
        float esc = 1.0f;
        if (biased) esc = 1.0f + *epsp;
#pragma unroll
        for (int mt = 0; mt < 2; mt++) {
#pragma unroll
            for (int nt = 0; nt < 8; nt++) {
                int col = wn + nt * 8 + tg * 2;
                int r0 = br + wm + mt * 16 + g;
                float v0 = acc[mt][nt][0], v1 = acc[mt][nt][1];
                float v2 = acc[mt][nt][2], v3 = acc[mt][nt][3];
                if (biased) {
                    float b0 = bias[col], b1 = bias[col + 1];
                    v0 = esc * fmaxf(v0 + b0, 0.f);
                    v1 = esc * fmaxf(v1 + b1, 0.f);
                    v2 = esc * fmaxf(v2 + b0, 0.f);
                    v3 = esc * fmaxf(v3 + b1, 0.f);
                }
                if (r0 < n)     *(float2*)(C + (size_t)r0 * DIM + col)       = make_float2(v0, v1);
                if (r0 + 8 < n) *(float2*)(C + (size_t)(r0 + 8) * DIM + col) = make_float2(v2, v3);
            }
        }
    }
}

// ---------------- fused aggregation + epilogue ----------------
__device__ __forceinline__ float4 relu4(float4 v) {
    return make_float4(fmaxf(v.x, 0.f), fmaxf(v.y, 0.f), fmaxf(v.z, 0.f), fmaxf(v.w, 0.f));
}
__device__ __forceinline__ void add4(float4& a, const float4 b) {
    a.x += b.x; a.y += b.y; a.z += b.z; a.w += b.w;
}

__global__ void aggregate_k(const float* __restrict__ xt, const float* __restrict__ souts,
                            const float* __restrict__ z1, const float* __restrict__ z2,
                            const float* __restrict__ z3, const float* __restrict__ bk_t,
                            int kmax, float* __restrict__ xnext, int n) {
    int warp = (blockIdx.x * blockDim.x + threadIdx.x) >> 5;
    if (warp >= n) return;
    int lane = threadIdx.x & 31;

    float4 acc1 = make_float4(0.f, 0.f, 0.f, 0.f);
    float4 acc2 = acc1, acc3 = acc1;

    int beg = g_rowptr[warp];
    int deg = g_rowptr[warp + 1] - beg;

    for (int base = 0; base < deg; base += 32) {
        int m = min(32, deg - base);
        unsigned ew = 0;
        if (base + lane < deg) ew = g_edges[beg + base + lane];
        for (int i = 0; i < m; i++) {
            unsigned p = __shfl_sync(0xffffffffu, ew, i);
            int a = (int)(p >> 16);
            if (a > kmax) continue;
            int src = (int)(p & 0xFFFFu);
            const float4* zp = (const float4*)((a == 1) ? z1 : (a == 2) ? z2 : z3);
            float4 v = zp[(size_t)src * 32 + lane];
            if (a == 1) add4(acc1, v);
            else if (a == 2) add4(acc2, v);
            else add4(acc3, v);
        }
    }

    float4 o = ((const float4*)souts)[(size_t)warp * 32 + lane];
    {
        float4 b = ((const float4*)(bk_t + 0 * DIM))[lane];
        add4(acc1, b);
        add4(o, relu4(acc1));
    }
    if (kmax >= 2) {
        float4 b = ((const float4*)(bk_t + 1 * DIM))[lane];
        add4(acc2, b);
        add4(o, relu4(acc2));
    }
    if (kmax >= 3) {
        float4 b = ((const float4*)(bk_t + 2 * DIM))[lane];
        add4(acc3, b);
        add4(o, relu4(acc3));
    }
    float4 xv = ((const float4*)xt)[(size_t)warp * 32 + lane];
    float4 h = relu4(o);
    add4(xv, h);
    ((float4*)xnext)[(size_t)warp * 32 + lane] = xv;
}

// ---------------- launch ----------------
extern "C" void kernel_launch(void* const* d_in, const int* in_sizes, int n_in,
                              void* d_out, int out_size) {
    const float* x   = (const float*)d_in[0];
    const int*   ei  = (const int*)d_in[1];   // [2, E]
    const int*   ea  = (const int*)d_in[2];   // [E]
    const float* Ws  = (const float*)d_in[3];
    const float* bs  = (const float*)d_in[4];
    const float* Wk  = (const float*)d_in[5];
    const float* bk  = (const float*)d_in[6];
    const float* eps = (const float*)d_in[7];
    float* out = (float*)d_out;

    int n = in_sizes[0] / DIM;
    int e = in_sizes[2];
    const int* src = ei;
    const int* dst = ei + e;

    float *p_x1, *p_x2, *p_sout, *p_z0, *p_z1, *p_z2;
    cudaGetSymbolAddress((void**)&p_x1, g_x1);
    cudaGetSymbolAddress((void**)&p_x2, g_x2);
    cudaGetSymbolAddress((void**)&p_sout, g_sout);
    cudaGetSymbolAddress((void**)&p_z0, g_z0);
    cudaGetSymbolAddress((void**)&p_z1, g_z1);
    cudaGetSymbolAddress((void**)&p_z2, g_z2);
    __nv_bfloat16 *p_wh, *p_wl;
    cudaGetSymbolAddress((void**)&p_wh, g_whT);
    cudaGetSymbolAddress((void**)&p_wl, g_wlT);

    cudaFuncSetAttribute(mma_gemm2_k, cudaFuncAttributeMaxDynamicSharedMemorySize, SM2_BYTES);

    // ----- weight preprocessing + CSR build -----
    convw_k<<<12, 256>>>(Ws, Wk);
    zero_count_k<<<(n + 255) / 256, 256>>>(n);
    count_k<<<(e + 255) / 256, 256>>>(dst, e);
    int nb = (n + 1023) / 1024;
    scan1_k<<<nb, 256>>>(n);
    scan2_k<<<1, 64>>>(nb);
    scan3_k<<<(n + 255) / 256, 256>>>(n, e);
    place_k<<<(e + 255) / 256, 256>>>(src, dst, ea, e);

    const float* xs[4];
    xs[0] = x;
    xs[1] = p_x1;
    xs[2] = p_x2;
    xs[3] = out;

    int gemm_grid = (n + 63) / 64;
    int agg_grid = (n * 32 + 255) / 256;
    float* zbuf[3] = {p_z0, p_z1, p_z2};

    for (int t = 0; t < LAY; t++) {
        // combined launch: sout = (1+eps)*relu(xt@Ws[t]+bs[t])  AND  z0 = xt@Wk[t][0]
        int slot1 = 3 + t * LAY + 0;
        mma_gemm2_k<<<gemm_grid, 128, SM2_BYTES>>>(
            xs[t],
            p_wh + (size_t)t * DIM * DIM, p_wl + (size_t)t * DIM * DIM, p_sout,
            bs + t * DIM, eps + t,
            p_wh + (size_t)slot1 * DIM * DIM, p_wl + (size_t)slot1 * DIM * DIM, zbuf[0],
            n);
        // remaining z_k (k >= 2) each use a different A -> single-product launches
        for (int k = 2; k <= t + 1; k++) {
            int slot = 3 + t * LAY + (k - 1);
            mma_gemm2_k<<<gemm_grid, 128, SM2_BYTES>>>(
                xs[t - (k - 1)],
                p_wh + (size_t)slot * DIM * DIM, p_wl + (size_t)slot * DIM * DIM, zbuf[k - 1],
                nullptr, nullptr,
                nullptr, nullptr, nullptr,
                n);
        }
        aggregate_k<<<agg_grid, 256>>>(xs[t], p_sout, p_z0, p_z1, p_z2,
                                       bk + (size_t)t * LAY * DIM, t + 1,
                                       (float*)xs[t + 1], n);
    }
}